// round 14
// baseline (speedup 1.0000x reference)
#include <cuda_runtime.h>
#include <cuda_fp16.h>
#include <math.h>
#include <cstdint>

#define NT 8192   // B*C tokens
#define HD 1024
#define TT 3
#define EE 6

constexpr int KB = HD / 64;  // k-blocks per operand row (tiles of 64 halves = 128 B)

// ---- scratch (device globals; no allocation allowed) ----
// Tiled-swizzled fp16 operands: tile = 128 rows x 128 B (8192 halves),
// tile index = row_blk * KB + k_blk; within tile: off = r*128 + (2c ^ ((r&7)<<4)).
__device__ __align__(128) __half g_ench[NT * HD];
__device__ __align__(128) __half g_x1h[NT * HD];
__device__ float  g_x[NT * HD];          // fp32 shared-bottom out, LINEAR (for gates)
__device__ __align__(128) __half g_xh[NT * HD];
__device__ __align__(128) __half g_wt1h[HD * HD];
__device__ __align__(128) __half g_wt2h[HD * HD];
__device__ __align__(128) __half g_wteh[EE * HD * HD];
__device__ float g_gates[NT * TT * EE];
__device__ float g_s[NT * EE * TT];
__device__ float g_w2t[EE * HD * TT];
__device__ float g_b2dot[EE * TT];
__device__ float g_imp[TT * EE];
__device__ float g_load[TT * EE];
__device__ float g_bce[1];

// ======================= helpers =======================
__device__ __forceinline__ uint32_t smem_u32(const void* p) {
    uint32_t a;
    asm("{ .reg .u64 t; cvta.to.shared.u64 t, %1; cvt.u32.u64 %0, t; }" : "=r"(a) : "l"(p));
    return a;
}
#define MBAR_INIT(a, c) asm volatile("mbarrier.init.shared.b64 [%0], %1;" :: "r"((uint32_t)(a)), "r"((uint32_t)(c)) : "memory")
#define MBAR_INVAL(a) asm volatile("mbarrier.inval.shared.b64 [%0];" :: "r"((uint32_t)(a)) : "memory")
#define MBAR_EXPECT_TX(a, n) asm volatile("mbarrier.arrive.expect_tx.shared.b64 _, [%0], %1;" :: "r"((uint32_t)(a)), "r"((uint32_t)(n)) : "memory")
#define MBAR_ARRIVE(a) asm volatile("mbarrier.arrive.shared.b64 _, [%0];" :: "r"((uint32_t)(a)) : "memory")
#define MBAR_WAIT(a, ph) do {                                              \
    uint32_t _m = (uint32_t)(a), _p = (uint32_t)(ph), _d;                  \
    asm volatile("{ .reg .pred p; mbarrier.try_wait.parity.acquire.cta.shared::cta.b64 p, [%1], %2; selp.b32 %0,1,0,p; }" \
                 : "=r"(_d) : "r"(_m), "r"(_p) : "memory");                \
    if (!_d) {                                                             \
        asm volatile("{ .reg .pred P1; WL%=: mbarrier.try_wait.parity.acquire.cta.shared::cta.b64 P1, [%0], %1, 0x989680; @P1 bra.uni WD%=; bra.uni WL%=; WD%=: }" \
                     :: "r"(_m), "r"(_p) : "memory");                      \
    }                                                                      \
} while (0)
__device__ __forceinline__ void bulk_ld(uint32_t dst, const void* src, uint32_t bytes,
                                        uint32_t mbar) {
    asm volatile(
        "cp.async.bulk.shared::cluster.global.mbarrier::complete_tx::bytes [%0], [%1], %2, [%3];"
        :: "r"(dst), "l"(src), "r"(bytes), "r"(mbar) : "memory");
}

__device__ __forceinline__ void mma16(float* c, const uint32_t* a, const uint32_t* b) {
    asm volatile(
        "mma.sync.aligned.m16n8k16.row.col.f32.f16.f16.f32 "
        "{%0,%1,%2,%3}, {%4,%5,%6,%7}, {%8,%9}, {%0,%1,%2,%3};"
        : "+f"(c[0]), "+f"(c[1]), "+f"(c[2]), "+f"(c[3])
        : "r"(a[0]), "r"(a[1]), "r"(a[2]), "r"(a[3]), "r"(b[0]), "r"(b[1]));
}
__device__ __forceinline__ void ldsm4(uint32_t* r, uint32_t addr) {
    asm volatile("ldmatrix.sync.aligned.m8n8.x4.shared.b16 {%0,%1,%2,%3}, [%4];"
                 : "=r"(r[0]), "=r"(r[1]), "=r"(r[2]), "=r"(r[3]) : "r"(addr));
}

// half-index offset of element (r, c-half) inside tiled-swizzled operand
__device__ __forceinline__ size_t tile_off(int row_blk, int k_blk, int r, int c) {
    uint32_t b = (uint32_t)(2 * c) ^ (uint32_t)((r & 7) << 4);
    return ((size_t)(row_blk * KB + k_blk) << 13) + ((uint32_t)r << 6) + (b >> 1);
}

// ======================= fp16 mma.sync GEMM =======================
// CTA tile 256(M) x 128(N), 512 threads, warp grid 4(M) x 4(N), warp tile 64x32.
constexpr int BM = 256, BN = 128;
constexpr int BKH = 64;                  // k-halves per slab = one tile column
constexpr int NS = HD / BKH;             // 16 slabs
constexpr int TILE_BYTES = 16384;
constexpr int STG_B = 3 * TILE_BYTES;    // A0 + A1 + B tiles = 48 KB
constexpr int CTRL = 1024;               // mbars: data at +0,8,16; free at +32,40,48
constexpr int GSMEM = CTRL + 3 * STG_B;  // 148480 B (1 CTA/SM)
constexpr int NTHREADS = 512;

// MODE 0: fc2 (A=g_x1h -> g_x fp32 + g_xh tiled)  MODE 1: fc1 (A=g_ench -> g_x1h tiled, relu)
// MODE 2: expert (A=g_xh, bias+relu, fused s-epilogue)
template <int MODE>
__global__ __launch_bounds__(NTHREADS, 1) void gemm_mma(const float* __restrict__ bias_in) {
    extern __shared__ __align__(16) char smb[];
    const uint32_t sb = smem_u32(smb);
    float* smf = (float*)smb;
    const int tid = threadIdx.x;
    const int wid = tid >> 5, lane = tid & 31;
    const int wm = wid >> 2, wn = wid & 3;     // warp grid 4(M) x 4(N)
    const int gr = lane >> 2, tq = lane & 3;   // quad row / quad col
    const int e = blockIdx.z;
    const int rb = blockIdx.y * BM, cb = blockIdx.x * BN;

    const __half* A = (MODE == 1) ? g_ench : (MODE == 0 ? g_x1h : g_xh);
    const __half* Bw = (MODE == 1) ? g_wt1h
                                   : (MODE == 0 ? g_wt2h : g_wteh + (size_t)e * HD * HD);
    const float* bp = bias_in + (MODE == 2 ? (size_t)e * HD : 0);

    float C[4][4][4];
#pragma unroll
    for (int i = 0; i < 4; i++)
#pragma unroll
        for (int j = 0; j < 4; j++)
#pragma unroll
            for (int q = 0; q < 4; q++) C[i][j][q] = 0.f;

    // ldmatrix lane addressing (pre-swizzled tiles; swz constant per lane).
    // A region: 256 contiguous rows (two 128-row tiles back-to-back), row R at R*128.
    const uint32_t swz = (uint32_t)((lane & 7) << 4);
    const uint32_t a_row_off = (uint32_t)((wm * 64 + (lane & 15)) * 128);
    const uint32_t a_seg = (uint32_t)((lane >> 4) << 4);
    const uint32_t b_row_off =
        (uint32_t)((wn * 32 + ((lane >> 4) << 3) + (lane & 7)) * 128);
    const uint32_t b_seg = (uint32_t)(((lane >> 3) & 1) << 4);

    if (tid == 0) {
        MBAR_INIT(sb + 0, 1);     // data[0]
        MBAR_INIT(sb + 8, 1);     // data[1]
        MBAR_INIT(sb + 16, 1);    // data[2]
        MBAR_INIT(sb + 32, 16);   // free[0]
        MBAR_INIT(sb + 40, 16);   // free[1]
        MBAR_INIT(sb + 48, 16);   // free[2]
    }
    __syncthreads();

    auto issue = [&](int p, int s) {  // load slab p into stage s (single thread)
        uint32_t mb = sb + 8 * s;
        uint32_t stg = sb + CTRL + s * STG_B;
        MBAR_EXPECT_TX(mb, (uint32_t)STG_B);
        bulk_ld(stg, A + (((size_t)((blockIdx.y * 2 + 0) * KB + p)) << 13), TILE_BYTES, mb);
        bulk_ld(stg + TILE_BYTES,
                A + (((size_t)((blockIdx.y * 2 + 1) * KB + p)) << 13), TILE_BYTES, mb);
        bulk_ld(stg + 2 * TILE_BYTES,
                Bw + (((size_t)(blockIdx.x * KB + p)) << 13), TILE_BYTES, mb);
    };

    if (tid == 0) { issue(0, 0); issue(1, 1); }

    for (int i = 0; i < NS; i++) {
        const int s = i % 3;
        // producer: issue slab i+2 into its stage as soon as that stage is free
        if (tid == 0 && i + 2 < NS) {
            const int j = i + 2;
            if (j >= 3) MBAR_WAIT(sb + 32 + 8 * (j % 3), ((j / 3) - 1) & 1);
            issue(j, j % 3);
        }
        MBAR_WAIT(sb + 8 * s, (i / 3) & 1);   // slab i data resident

        const uint32_t As_u = sb + CTRL + s * STG_B;
        const uint32_t Bs_u = As_u + 2 * TILE_BYTES;
#pragma unroll
        for (int ks = 0; ks < 4; ks++) {
            const uint32_t a_col = ((uint32_t)(ks * 32) + a_seg) ^ swz;
            const uint32_t b_col = ((uint32_t)(ks * 32) + b_seg) ^ swz;
            uint32_t a[4][4], b[2][4];
#pragma unroll
            for (int mt = 0; mt < 4; mt++)
                ldsm4(a[mt], As_u + a_row_off + (uint32_t)(mt * 2048) + a_col);
#pragma unroll
            for (int np = 0; np < 2; np++)
                ldsm4(b[np], Bs_u + b_row_off + (uint32_t)(np * 2048) + b_col);
#pragma unroll
            for (int mt = 0; mt < 4; mt++) {
#pragma unroll
                for (int np = 0; np < 2; np++) {
                    mma16(C[mt][2 * np + 0], a[mt], &b[np][0]);
                    mma16(C[mt][2 * np + 1], a[mt], &b[np][2]);
                }
            }
        }
        if (lane == 0) MBAR_ARRIVE(sb + 32 + 8 * s);  // this warp done with stage s
    }
    __syncthreads();  // all warps past the loop; no pending stage reuse
    if (tid == 0) {
        MBAR_INVAL(sb + 0);  MBAR_INVAL(sb + 8);  MBAR_INVAL(sb + 16);
        MBAR_INVAL(sb + 32); MBAR_INVAL(sb + 40); MBAR_INVAL(sb + 48);
    }
    __syncthreads();

    // ---- epilogue ----
    if (MODE == 2) {
        float* w2t_s = smf;            // 384
        float* bias_s = smf + 384;     // 128
        float* sred = smf + 512;       // 256*12 = 3072
        if (tid < 128) bias_s[tid] = bp[cb + tid];
        for (int idx = tid; idx < 384; idx += NTHREADS)
            w2t_s[idx] = g_w2t[(size_t)e * HD * 3 + (size_t)cb * 3 + idx];
        __syncthreads();
#pragma unroll
        for (int mt = 0; mt < 4; mt++) {
#pragma unroll
            for (int pair = 0; pair < 2; pair++) {
                float p0 = 0.f, p1 = 0.f, p2 = 0.f;
#pragma unroll
                for (int nt = 0; nt < 4; nt++) {
                    int cl = wn * 32 + nt * 8 + tq * 2;
                    float h0 = fmaxf(C[mt][nt][pair * 2 + 0] + bias_s[cl], 0.f);
                    float h1 = fmaxf(C[mt][nt][pair * 2 + 1] + bias_s[cl + 1], 0.f);
                    p0 += h0 * w2t_s[cl * 3 + 0] + h1 * w2t_s[(cl + 1) * 3 + 0];
                    p1 += h0 * w2t_s[cl * 3 + 1] + h1 * w2t_s[(cl + 1) * 3 + 1];
                    p2 += h0 * w2t_s[cl * 3 + 2] + h1 * w2t_s[(cl + 1) * 3 + 2];
                }
                p0 += __shfl_down_sync(0xffffffffu, p0, 2);
                p0 += __shfl_down_sync(0xffffffffu, p0, 1);
                p1 += __shfl_down_sync(0xffffffffu, p1, 2);
                p1 += __shfl_down_sync(0xffffffffu, p1, 1);
                p2 += __shfl_down_sync(0xffffffffu, p2, 2);
                p2 += __shfl_down_sync(0xffffffffu, p2, 1);
                if (tq == 0) {
                    int rl = wm * 64 + mt * 16 + pair * 8 + gr;
                    sred[rl * 12 + wn * 3 + 0] = p0;
                    sred[rl * 12 + wn * 3 + 1] = p1;
                    sred[rl * 12 + wn * 3 + 2] = p2;
                }
            }
        }
        __syncthreads();
        if (tid < 256) {
#pragma unroll
            for (int t = 0; t < 3; t++) {
                float s = sred[tid * 12 + t] + sred[tid * 12 + 3 + t] +
                          sred[tid * 12 + 6 + t] + sred[tid * 12 + 9 + t];
                atomicAdd(&g_s[(size_t)(rb + tid) * 18 + e * 3 + t], s);
            }
        }
    } else {
        float* bias_s = smf;
        if (tid < 128) bias_s[tid] = bp[cb + tid];
        __syncthreads();
#pragma unroll
        for (int mt = 0; mt < 4; mt++) {
#pragma unroll
            for (int nt = 0; nt < 4; nt++) {
                int r0 = wm * 64 + mt * 16 + gr;         // within-CTA rows (<256)
                int cl = wn * 32 + nt * 8 + tq * 2;
                int kcol = cb + cl;
                int k_blk = kcol >> 6, c = kcol & 63;
                float v0 = C[mt][nt][0] + bias_s[cl];
                float v1 = C[mt][nt][1] + bias_s[cl + 1];
                float v2 = C[mt][nt][2] + bias_s[cl];
                float v3 = C[mt][nt][3] + bias_s[cl + 1];
                if (MODE == 1) {
                    v0 = fmaxf(v0, 0.f); v1 = fmaxf(v1, 0.f);
                    v2 = fmaxf(v2, 0.f); v3 = fmaxf(v3, 0.f);
                }
                __half2 h0 = __halves2half2(__float2half_rn(v0), __float2half_rn(v1));
                __half2 h1 = __halves2half2(__float2half_rn(v2), __float2half_rn(v3));
                __half* outh = (MODE == 1) ? g_x1h : g_xh;
                int rg0 = rb + r0, rg1 = rb + r0 + 8;
                *(__half2*)(outh + tile_off(rg0 >> 7, k_blk, rg0 & 127, c)) = h0;
                *(__half2*)(outh + tile_off(rg1 >> 7, k_blk, rg1 & 127, c)) = h1;
                if (MODE == 0) {
                    *(float2*)(g_x + (size_t)rg0 * HD + kcol) = make_float2(v0, v1);
                    *(float2*)(g_x + (size_t)rg1 * HD + kcol) = make_float2(v2, v3);
                }
            }
        }
    }
}

// ======================= small kernels =======================
// encs fp32 -> tiled-swizzled fp16 (one 16B segment per thread)
__global__ void conv_h_k(const float* __restrict__ in, __half* __restrict__ out) {
    int gid = blockIdx.x * 256 + threadIdx.x;       // segment index, NT*HD/8 total
    int n = gid >> 7;                               // HD/8 = 128 segs per row
    int s8 = gid & 127;
    int k = s8 * 8;
    float4 v0 = *(const float4*)(in + (size_t)n * HD + k);
    float4 v1 = *(const float4*)(in + (size_t)n * HD + k + 4);
    __half2 h[4];
    h[0] = __halves2half2(__float2half_rn(v0.x), __float2half_rn(v0.y));
    h[1] = __halves2half2(__float2half_rn(v0.z), __float2half_rn(v0.w));
    h[2] = __halves2half2(__float2half_rn(v1.x), __float2half_rn(v1.y));
    h[3] = __halves2half2(__float2half_rn(v1.z), __float2half_rn(v1.w));
    *(uint4*)(out + tile_off(n >> 7, k >> 6, n & 127, k & 63)) = *(uint4*)h;
}

// W[k][n] fp32 -> WT tiled-swizzled fp16 (WT row = n, col = k)
__global__ void transpose_h_k(const float* __restrict__ W, __half* __restrict__ WT) {
    __shared__ float t[32][33];
    const float* Ws = W + (size_t)blockIdx.z * HD * HD;
    __half* Ts = WT + (size_t)blockIdx.z * HD * HD;
    int bx = blockIdx.x * 32, by = blockIdx.y * 32;
#pragma unroll
    for (int j = 0; j < 4; j++)
        t[threadIdx.y + 8 * j][threadIdx.x] =
            Ws[(size_t)(by + threadIdx.y + 8 * j) * HD + bx + threadIdx.x];
    __syncthreads();
#pragma unroll
    for (int j = 0; j < 4; j++) {
        int nrow = bx + threadIdx.y + 8 * j;
        int kcol = by + threadIdx.x;
        Ts[tile_off(nrow >> 7, kcol >> 6, nrow & 127, kcol & 63)] =
            __float2half_rn(t[threadIdx.x][threadIdx.y + 8 * j]);
    }
}

__global__ void zero_kernel() {
    int idx = blockIdx.x * 256 + threadIdx.x;
    if (idx < NT * EE * TT) g_s[idx] = 0.f;
    if (idx < TT * EE) { g_imp[idx] = 0.f; g_load[idx] = 0.f; }
    if (idx == 0) g_bce[0] = 0.f;
}

__global__ __launch_bounds__(256) void w2t_kernel(const float* __restrict__ w2,
                                                  const float* __restrict__ tw) {
    int g = blockIdx.x * 256 + threadIdx.x;
    int gw = g >> 5, lane = g & 31;
    if (gw >= EE * HD) return;
    const float* row = w2 + (size_t)gw * HD;
#pragma unroll
    for (int t = 0; t < TT; t++) {
        float a = 0.f;
        for (int o = lane; o < HD; o += 32) a += row[o] * tw[t * HD + o];
#pragma unroll
        for (int off = 16; off; off >>= 1) a += __shfl_down_sync(0xffffffffu, a, off);
        if (lane == 0) g_w2t[(size_t)gw * TT + t] = a;
    }
}

__global__ void b2dot_kernel(const float* __restrict__ b2, const float* __restrict__ tw) {
    int i = threadIdx.x;
    if (i < EE * TT) {
        int e = i / TT, t = i - TT * e;
        float a = 0.f;
        for (int o = 0; o < HD; o++) a += b2[e * HD + o] * tw[t * HD + o];
        g_b2dot[i] = a;
    }
}

__global__ __launch_bounds__(256) void gates_kernel(const float* __restrict__ wg) {
    int warp = threadIdx.x >> 5, lane = threadIdx.x & 31;
    int n = blockIdx.x * 8 + warp;
    const float* xr = g_x + (size_t)n * HD;
    float xv[32];
#pragma unroll
    for (int i = 0; i < 32; i++) xv[i] = xr[i * 32 + lane];
    float lg[18];
    for (int te = 0; te < 18; te++) {
        int t = te / 6, e = te - 6 * t;
        float acc = 0.f;
#pragma unroll
        for (int i = 0; i < 32; i++)
            acc += xv[i] * wg[((size_t)t * HD + i * 32 + lane) * EE + e];
#pragma unroll
        for (int off = 16; off; off >>= 1) acc += __shfl_down_sync(0xffffffffu, acc, off);
        lg[te] = acc;
    }
    if (lane == 0) {
        for (int t = 0; t < TT; t++) {
            float v[6];
#pragma unroll
            for (int e = 0; e < 6; e++) v[e] = lg[t * 6 + e];
            bool sel[6] = {false, false, false, false, false, false};
            float m = -1e30f;
            for (int r = 0; r < 3; r++) {  // strict >: first index wins (jax top_k)
                int bi = 0; float bv = -1e30f;
                for (int e = 0; e < 6; e++)
                    if (!sel[e] && v[e] > bv) { bv = v[e]; bi = e; }
                sel[bi] = true;
                if (r == 0) m = bv;
            }
            float sum = 0.f, gv[6];
            for (int e = 0; e < 6; e++) { gv[e] = sel[e] ? expf(v[e] - m) : 0.f; sum += gv[e]; }
            float inv = 1.f / sum;
            for (int e = 0; e < 6; e++) {
                float gg = gv[e] * inv;
                g_gates[(size_t)n * 18 + t * 6 + e] = gg;
                if (sel[e]) {
                    atomicAdd(&g_imp[t * 6 + e], gg);
                    atomicAdd(&g_load[t * 6 + e], 1.f);
                }
            }
        }
    }
}

__global__ void final_kernel(const float* __restrict__ scores,
                             const float* __restrict__ tower_b, float* __restrict__ out) {
    int b = blockIdx.x, c = threadIdx.x;
    int n = b * 64 + c;
    float sc[3];
#pragma unroll
    for (int t = 0; t < 3; t++) sc[t] = scores[(size_t)n * 3 + t];
    __shared__ float red[64];
    float mx[3];
    for (int t = 0; t < 3; t++) {
        red[c] = sc[t];
        __syncthreads();
        for (int off = 32; off; off >>= 1) {
            if (c < off) red[c] = fmaxf(red[c], red[c + off]);
            __syncthreads();
        }
        mx[t] = red[0];
        __syncthreads();
    }
    float zsum = 0.f, bsum = 0.f;
#pragma unroll
    for (int t = 0; t < 3; t++) {
        float z = tower_b[t];
#pragma unroll
        for (int e = 0; e < 6; e++)
            z += g_gates[(size_t)n * 18 + t * 6 + e] *
                 (g_s[(size_t)n * 18 + e * 3 + t] + g_b2dot[e * 3 + t]);
        float label = (sc[t] == mx[t]) ? 1.f : 0.f;
        bsum += fmaxf(z, 0.f) - z * label + log1pf(expf(-fabsf(z)));
        zsum += z;
    }
    out[1 + n] = 1.f / (1.f + expf(-zsum / 3.f));
    red[c] = bsum;
    __syncthreads();
    for (int off = 32; off; off >>= 1) {
        if (c < off) red[c] += red[c + off];
        __syncthreads();
    }
    if (c == 0) atomicAdd(&g_bce[0], red[0]);
}

__global__ void finalize_kernel(float* __restrict__ out) {
    if (threadIdx.x == 0 && blockIdx.x == 0) {
        float aux = 0.f;
        for (int t = 0; t < 3; t++) {
            for (int which = 0; which < 2; which++) {
                const float* v = which ? &g_load[t * 6] : &g_imp[t * 6];
                float m = 0.f;
                for (int e = 0; e < 6; e++) m += v[e];
                m *= (1.f / 6.f);
                float var = 0.f;
                for (int e = 0; e < 6; e++) { float d = v[e] - m; var += d * d; }
                var *= (1.f / 5.f);  // ddof=1
                aux += var / (m * m + 1e-10f);
            }
        }
        out[0] = g_bce[0] / 24576.f + 0.01f * aux;
    }
}

// ======================= launch =======================
extern "C" void kernel_launch(void* const* d_in, const int* in_sizes, int n_in,
                              void* d_out, int out_size) {
    const float* encs   = (const float*)d_in[0];
    const float* scores = (const float*)d_in[1];
    const float* fc1_w  = (const float*)d_in[2];
    const float* fc1_b  = (const float*)d_in[3];
    const float* fc2_w  = (const float*)d_in[4];
    const float* fc2_b  = (const float*)d_in[5];
    const float* w_gate = (const float*)d_in[6];
    const float* ew1    = (const float*)d_in[7];
    const float* eb1    = (const float*)d_in[8];
    const float* ew2    = (const float*)d_in[9];
    const float* eb2    = (const float*)d_in[10];
    const float* tw     = (const float*)d_in[11];
    const float* tb     = (const float*)d_in[12];
    float* out = (float*)d_out;

    cudaFuncSetAttribute(gemm_mma<0>, cudaFuncAttributeMaxDynamicSharedMemorySize, GSMEM);
    cudaFuncSetAttribute(gemm_mma<1>, cudaFuncAttributeMaxDynamicSharedMemorySize, GSMEM);
    cudaFuncSetAttribute(gemm_mma<2>, cudaFuncAttributeMaxDynamicSharedMemorySize, GSMEM);

    __half *ench, *wt1h, *wt2h, *wteh;
    cudaGetSymbolAddress((void**)&ench, g_ench);
    cudaGetSymbolAddress((void**)&wt1h, g_wt1h);
    cudaGetSymbolAddress((void**)&wt2h, g_wt2h);
    cudaGetSymbolAddress((void**)&wteh, g_wteh);

    dim3 gfc(HD / BN, NT / BM, 1);        // (8, 32)
    dim3 ge(HD / BN, NT / BM, EE);        // (8, 32, 6)

    zero_kernel<<<(NT * EE * TT + 255) / 256, 256>>>();
    conv_h_k<<<NT * HD / 8 / 256, 256>>>(encs, ench);
    transpose_h_k<<<dim3(32, 32, 1), dim3(32, 8)>>>(fc1_w, wt1h);
    transpose_h_k<<<dim3(32, 32, 1), dim3(32, 8)>>>(fc2_w, wt2h);
    gemm_mma<1><<<gfc, NTHREADS, GSMEM>>>(fc1_b);                          // x1
    gemm_mma<0><<<gfc, NTHREADS, GSMEM>>>(fc2_b);                          // x
    transpose_h_k<<<dim3(32, 32, EE), dim3(32, 8)>>>(ew1, wteh);
    w2t_kernel<<<(EE * HD * 32 + 255) / 256, 256>>>(ew2, tw);
    b2dot_kernel<<<1, 32>>>(eb2, tw);
    gates_kernel<<<NT / 8, 256>>>(w_gate);
    gemm_mma<2><<<ge, NTHREADS, GSMEM>>>(eb1);                             // experts
    final_kernel<<<128, 64>>>(scores, tb, out);
    finalize_kernel<<<1, 32>>>(out);
}

// round 15
// speedup vs baseline: 1.1372x; 1.1372x over previous
#include <cuda_runtime.h>
#include <cuda_fp16.h>
#include <math.h>
#include <cstdint>

#define NT 8192   // B*C tokens
#define HD 1024
#define TT 3
#define EE 6

constexpr int KB = HD / 64;  // k-blocks per operand row (tiles of 64 halves = 128 B)

// ---- scratch (device globals; no allocation allowed) ----
// Tiled-swizzled fp16 operands: tile = 128 rows x 128 B (8192 halves),
// tile index = row_blk * KB + k_blk; within tile: off = r*128 + (2c ^ ((r&7)<<4)).
__device__ __align__(128) __half g_ench[NT * HD];
__device__ __align__(128) __half g_x1h[NT * HD];
__device__ float  g_x[NT * HD];          // fp32 shared-bottom out, LINEAR (for gates)
__device__ __align__(128) __half g_xh[NT * HD];
__device__ __align__(128) __half g_wt1h[HD * HD];
__device__ __align__(128) __half g_wt2h[HD * HD];
__device__ __align__(128) __half g_wteh[EE * HD * HD];
__device__ float g_gates[NT * TT * EE];
__device__ float g_s[NT * EE * TT];
__device__ float g_w2t[EE * HD * TT];
__device__ float g_b2dot[EE * TT];
__device__ float g_imp[TT * EE];
__device__ float g_load[TT * EE];
__device__ float g_bce[1];

// ======================= helpers =======================
__device__ __forceinline__ uint32_t smem_u32(const void* p) {
    uint32_t a;
    asm("{ .reg .u64 t; cvta.to.shared.u64 t, %1; cvt.u32.u64 %0, t; }" : "=r"(a) : "l"(p));
    return a;
}
#define MBAR_INIT(a, c) asm volatile("mbarrier.init.shared.b64 [%0], %1;" :: "r"((uint32_t)(a)), "r"((uint32_t)(c)) : "memory")
#define MBAR_INVAL(a) asm volatile("mbarrier.inval.shared.b64 [%0];" :: "r"((uint32_t)(a)) : "memory")
#define MBAR_EXPECT_TX(a, n) asm volatile("mbarrier.arrive.expect_tx.shared.b64 _, [%0], %1;" :: "r"((uint32_t)(a)), "r"((uint32_t)(n)) : "memory")
#define MBAR_ARRIVE(a) asm volatile("mbarrier.arrive.shared.b64 _, [%0];" :: "r"((uint32_t)(a)) : "memory")
#define MBAR_WAIT(a, ph) do {                                              \
    uint32_t _m = (uint32_t)(a), _p = (uint32_t)(ph), _d;                  \
    asm volatile("{ .reg .pred p; mbarrier.try_wait.parity.acquire.cta.shared::cta.b64 p, [%1], %2; selp.b32 %0,1,0,p; }" \
                 : "=r"(_d) : "r"(_m), "r"(_p) : "memory");                \
    if (!_d) {                                                             \
        asm volatile("{ .reg .pred P1; WL%=: mbarrier.try_wait.parity.acquire.cta.shared::cta.b64 P1, [%0], %1, 0x989680; @P1 bra.uni WD%=; bra.uni WL%=; WD%=: }" \
                     :: "r"(_m), "r"(_p) : "memory");                      \
    }                                                                      \
} while (0)
__device__ __forceinline__ void bulk_ld(uint32_t dst, const void* src, uint32_t bytes,
                                        uint32_t mbar) {
    asm volatile(
        "cp.async.bulk.shared::cluster.global.mbarrier::complete_tx::bytes [%0], [%1], %2, [%3];"
        :: "r"(dst), "l"(src), "r"(bytes), "r"(mbar) : "memory");
}

__device__ __forceinline__ void mma16(float* c, const uint32_t* a, const uint32_t* b) {
    asm volatile(
        "mma.sync.aligned.m16n8k16.row.col.f32.f16.f16.f32 "
        "{%0,%1,%2,%3}, {%4,%5,%6,%7}, {%8,%9}, {%0,%1,%2,%3};"
        : "+f"(c[0]), "+f"(c[1]), "+f"(c[2]), "+f"(c[3])
        : "r"(a[0]), "r"(a[1]), "r"(a[2]), "r"(a[3]), "r"(b[0]), "r"(b[1]));
}
__device__ __forceinline__ void ldsm4(uint32_t* r, uint32_t addr) {
    asm volatile("ldmatrix.sync.aligned.m8n8.x4.shared.b16 {%0,%1,%2,%3}, [%4];"
                 : "=r"(r[0]), "=r"(r[1]), "=r"(r[2]), "=r"(r[3]) : "r"(addr));
}

// half-index offset of element (r, c-half) inside tiled-swizzled operand
__device__ __forceinline__ size_t tile_off(int row_blk, int k_blk, int r, int c) {
    uint32_t b = (uint32_t)(2 * c) ^ (uint32_t)((r & 7) << 4);
    return ((size_t)(row_blk * KB + k_blk) << 13) + ((uint32_t)r << 6) + (b >> 1);
}

// ======================= fp16 mma.sync GEMM (round-13 config) =======================
constexpr int BM = 128, BN = 128;
constexpr int BKH = 64;                  // k-halves per slab = one tile column
constexpr int NS = HD / BKH;             // 16 slabs
constexpr int TILE_BYTES = 16384;
constexpr int STG_B = 2 * TILE_BYTES;    // A tile + B tile
constexpr int CTRL = 1024;               // mbars: data at +0,8,16; free at +32,40,48
constexpr int GSMEM = CTRL + 3 * STG_B;  // 99328 B (2 CTAs/SM)

// MODE 0: fc2 (A=g_x1h -> g_x fp32 + g_xh tiled)  MODE 1: fc1 (A=g_ench -> g_x1h tiled, relu)
// MODE 2: expert (A=g_xh, bias+relu, fused s-epilogue)
template <int MODE>
__global__ __launch_bounds__(256, 2) void gemm_mma(const float* __restrict__ bias_in) {
    extern __shared__ __align__(16) char smb[];
    const uint32_t sb = smem_u32(smb);
    float* smf = (float*)smb;
    const int tid = threadIdx.x;
    const int wid = tid >> 5, lane = tid & 31;
    const int wm = wid >> 2, wn = wid & 3;     // warp grid 2(M) x 4(N)
    const int gr = lane >> 2, tq = lane & 3;   // quad row / quad col
    const int e = blockIdx.z;
    const int rb = blockIdx.y * BM, cb = blockIdx.x * BN;

    const __half* A = (MODE == 1) ? g_ench : (MODE == 0 ? g_x1h : g_xh);
    const __half* Bw = (MODE == 1) ? g_wt1h
                                   : (MODE == 0 ? g_wt2h : g_wteh + (size_t)e * HD * HD);
    const float* bp = bias_in + (MODE == 2 ? (size_t)e * HD : 0);

    float C[4][4][4];
#pragma unroll
    for (int i = 0; i < 4; i++)
#pragma unroll
        for (int j = 0; j < 4; j++)
#pragma unroll
            for (int q = 0; q < 4; q++) C[i][j][q] = 0.f;

    // ldmatrix lane addressing (pre-swizzled tiles; swz constant per lane)
    const uint32_t swz = (uint32_t)((lane & 7) << 4);
    const uint32_t a_row_off = (uint32_t)((wm * 64 + (lane & 15)) * 128);
    const uint32_t a_seg = (uint32_t)((lane >> 4) << 4);
    const uint32_t b_row_off =
        (uint32_t)((wn * 32 + ((lane >> 4) << 3) + (lane & 7)) * 128);
    const uint32_t b_seg = (uint32_t)(((lane >> 3) & 1) << 4);

    if (tid == 0) {
        MBAR_INIT(sb + 0, 1);    // data[0]
        MBAR_INIT(sb + 8, 1);    // data[1]
        MBAR_INIT(sb + 16, 1);   // data[2]
        MBAR_INIT(sb + 32, 8);   // free[0]
        MBAR_INIT(sb + 40, 8);   // free[1]
        MBAR_INIT(sb + 48, 8);   // free[2]
    }
    __syncthreads();

    auto issue = [&](int p, int s) {  // load slab p into stage s (single thread)
        uint32_t mb = sb + 8 * s;
        uint32_t stg = sb + CTRL + s * STG_B;
        MBAR_EXPECT_TX(mb, (uint32_t)STG_B);
        bulk_ld(stg, A + (((size_t)(blockIdx.y * KB + p)) << 13), TILE_BYTES, mb);
        bulk_ld(stg + TILE_BYTES, Bw + (((size_t)(blockIdx.x * KB + p)) << 13), TILE_BYTES, mb);
    };

    if (tid == 0) { issue(0, 0); issue(1, 1); }

    for (int i = 0; i < NS; i++) {
        const int s = i % 3;
        // producer: issue slab i+2 into its stage as soon as that stage is free
        if (tid == 0 && i + 2 < NS) {
            const int j = i + 2;
            if (j >= 3) MBAR_WAIT(sb + 32 + 8 * (j % 3), ((j / 3) - 1) & 1);
            issue(j, j % 3);
        }
        MBAR_WAIT(sb + 8 * s, (i / 3) & 1);   // slab i data resident

        const uint32_t As_u = sb + CTRL + s * STG_B;
        const uint32_t Bs_u = As_u + TILE_BYTES;
#pragma unroll
        for (int ks = 0; ks < 4; ks++) {
            const uint32_t a_col = ((uint32_t)(ks * 32) + a_seg) ^ swz;
            const uint32_t b_col = ((uint32_t)(ks * 32) + b_seg) ^ swz;
            uint32_t a[4][4], b[2][4];
#pragma unroll
            for (int mt = 0; mt < 4; mt++)
                ldsm4(a[mt], As_u + a_row_off + (uint32_t)(mt * 2048) + a_col);
#pragma unroll
            for (int np = 0; np < 2; np++)
                ldsm4(b[np], Bs_u + b_row_off + (uint32_t)(np * 2048) + b_col);
#pragma unroll
            for (int mt = 0; mt < 4; mt++) {
#pragma unroll
                for (int np = 0; np < 2; np++) {
                    mma16(C[mt][2 * np + 0], a[mt], &b[np][0]);
                    mma16(C[mt][2 * np + 1], a[mt], &b[np][2]);
                }
            }
        }
        if (lane == 0) MBAR_ARRIVE(sb + 32 + 8 * s);  // this warp done with stage s
    }
    __syncthreads();  // all warps past the loop; no pending stage reuse
    if (tid == 0) {
        MBAR_INVAL(sb + 0);  MBAR_INVAL(sb + 8);  MBAR_INVAL(sb + 16);
        MBAR_INVAL(sb + 32); MBAR_INVAL(sb + 40); MBAR_INVAL(sb + 48);
    }
    __syncthreads();

    // ---- epilogue ----
    if (MODE == 2) {
        float* w2t_s = smf;            // 384
        float* bias_s = smf + 384;     // 128
        float* sred = smf + 512;       // 128*12
        if (tid < 128) bias_s[tid] = bp[cb + tid];
        for (int idx = tid; idx < 384; idx += 256)
            w2t_s[idx] = g_w2t[(size_t)e * HD * 3 + (size_t)cb * 3 + idx];
        __syncthreads();
#pragma unroll
        for (int mt = 0; mt < 4; mt++) {
#pragma unroll
            for (int pair = 0; pair < 2; pair++) {
                float p0 = 0.f, p1 = 0.f, p2 = 0.f;
#pragma unroll
                for (int nt = 0; nt < 4; nt++) {
                    int cl = wn * 32 + nt * 8 + tq * 2;
                    float h0 = fmaxf(C[mt][nt][pair * 2 + 0] + bias_s[cl], 0.f);
                    float h1 = fmaxf(C[mt][nt][pair * 2 + 1] + bias_s[cl + 1], 0.f);
                    p0 += h0 * w2t_s[cl * 3 + 0] + h1 * w2t_s[(cl + 1) * 3 + 0];
                    p1 += h0 * w2t_s[cl * 3 + 1] + h1 * w2t_s[(cl + 1) * 3 + 1];
                    p2 += h0 * w2t_s[cl * 3 + 2] + h1 * w2t_s[(cl + 1) * 3 + 2];
                }
                p0 += __shfl_down_sync(0xffffffffu, p0, 2);
                p0 += __shfl_down_sync(0xffffffffu, p0, 1);
                p1 += __shfl_down_sync(0xffffffffu, p1, 2);
                p1 += __shfl_down_sync(0xffffffffu, p1, 1);
                p2 += __shfl_down_sync(0xffffffffu, p2, 2);
                p2 += __shfl_down_sync(0xffffffffu, p2, 1);
                if (tq == 0) {
                    int rl = wm * 64 + mt * 16 + pair * 8 + gr;
                    sred[rl * 12 + wn * 3 + 0] = p0;
                    sred[rl * 12 + wn * 3 + 1] = p1;
                    sred[rl * 12 + wn * 3 + 2] = p2;
                }
            }
        }
        __syncthreads();
        if (tid < 128) {
#pragma unroll
            for (int t = 0; t < 3; t++) {
                float s = sred[tid * 12 + t] + sred[tid * 12 + 3 + t] +
                          sred[tid * 12 + 6 + t] + sred[tid * 12 + 9 + t];
                atomicAdd(&g_s[(size_t)(rb + tid) * 18 + e * 3 + t], s);
            }
        }
    } else {
        float* bias_s = smf;
        if (tid < 128) bias_s[tid] = bp[cb + tid];
        __syncthreads();
#pragma unroll
        for (int mt = 0; mt < 4; mt++) {
#pragma unroll
            for (int nt = 0; nt < 4; nt++) {
                int r0 = wm * 64 + mt * 16 + gr;         // within-CTA rows (<128)
                int cl = wn * 32 + nt * 8 + tq * 2;
                int kcol = cb + cl;
                int k_blk = kcol >> 6, c = kcol & 63;
                float v0 = C[mt][nt][0] + bias_s[cl];
                float v1 = C[mt][nt][1] + bias_s[cl + 1];
                float v2 = C[mt][nt][2] + bias_s[cl];
                float v3 = C[mt][nt][3] + bias_s[cl + 1];
                if (MODE == 1) {
                    v0 = fmaxf(v0, 0.f); v1 = fmaxf(v1, 0.f);
                    v2 = fmaxf(v2, 0.f); v3 = fmaxf(v3, 0.f);
                }
                __half2 h0 = __halves2half2(__float2half_rn(v0), __float2half_rn(v1));
                __half2 h1 = __halves2half2(__float2half_rn(v2), __float2half_rn(v3));
                __half* outh = (MODE == 1) ? g_x1h : g_xh;
                *(__half2*)(outh + tile_off(blockIdx.y, k_blk, r0, c)) = h0;
                *(__half2*)(outh + tile_off(blockIdx.y, k_blk, r0 + 8, c)) = h1;
                if (MODE == 0) {
                    int row = rb + r0;
                    *(float2*)(g_x + (size_t)row * HD + kcol) = make_float2(v0, v1);
                    *(float2*)(g_x + (size_t)(row + 8) * HD + kcol) = make_float2(v2, v3);
                }
            }
        }
    }
}

// ======================= fused prep kernel =======================
// One launch performs (all mutually independent):
//   role 0: zero g_s / g_imp / g_load / g_bce           blocks [0, 576)
//   role 1: encs fp32 -> tiled fp16                     blocks [576, 4672)
//   role 2: fc1_w transpose -> g_wt1h                   blocks [4672, 5696)
//   role 3: fc2_w transpose -> g_wt2h                   blocks [5696, 6720)
//   role 4: expert_w1 transposes -> g_wteh              blocks [6720, 12864)
//   role 5: w2t = w2 . tower_w^T                        blocks [12864, 13632)
//   role 6: b2dot                                       block  13632
constexpr int PB0 = 576, PB1 = PB0 + 4096, PB2 = PB1 + 1024, PB3 = PB2 + 1024,
              PB4 = PB3 + 6144, PB5 = PB4 + 768, PB6 = PB5 + 1;

__device__ void do_transpose(const float* __restrict__ Ws, __half* __restrict__ Ts,
                             int bx, int by, int tid) {
    __shared__ float t[32][33];
    int tx = tid & 31, ty = tid >> 5;  // (32, 8)
#pragma unroll
    for (int j = 0; j < 4; j++)
        t[ty + 8 * j][tx] = Ws[(size_t)(by + ty + 8 * j) * HD + bx + tx];
    __syncthreads();
#pragma unroll
    for (int j = 0; j < 4; j++) {
        int nrow = bx + ty + 8 * j;
        int kcol = by + tx;
        Ts[tile_off(nrow >> 7, kcol >> 6, nrow & 127, kcol & 63)] =
            __float2half_rn(t[tx][ty + 8 * j]);
    }
}

__global__ __launch_bounds__(256) void prep_kernel(
    const float* __restrict__ encs, const float* __restrict__ fc1_w,
    const float* __restrict__ fc2_w, const float* __restrict__ ew1,
    const float* __restrict__ ew2, const float* __restrict__ eb2,
    const float* __restrict__ tw) {
    const int b = blockIdx.x, tid = threadIdx.x;
    if (b < PB0) {
        int idx = b * 256 + tid;
        if (idx < NT * EE * TT) g_s[idx] = 0.f;
        if (idx < TT * EE) { g_imp[idx] = 0.f; g_load[idx] = 0.f; }
        if (idx == 0) g_bce[0] = 0.f;
    } else if (b < PB1) {
        int gid = (b - PB0) * 256 + tid;
        int n = gid >> 7, s8 = gid & 127, k = s8 * 8;
        float4 v0 = *(const float4*)(encs + (size_t)n * HD + k);
        float4 v1 = *(const float4*)(encs + (size_t)n * HD + k + 4);
        __half2 h[4];
        h[0] = __halves2half2(__float2half_rn(v0.x), __float2half_rn(v0.y));
        h[1] = __halves2half2(__float2half_rn(v0.z), __float2half_rn(v0.w));
        h[2] = __halves2half2(__float2half_rn(v1.x), __float2half_rn(v1.y));
        h[3] = __halves2half2(__float2half_rn(v1.z), __float2half_rn(v1.w));
        *(uint4*)(g_ench + tile_off(n >> 7, k >> 6, n & 127, k & 63)) = *(uint4*)h;
    } else if (b < PB2) {
        int r = b - PB1;
        do_transpose(fc1_w, g_wt1h, (r & 31) * 32, (r >> 5) * 32, tid);
    } else if (b < PB3) {
        int r = b - PB2;
        do_transpose(fc2_w, g_wt2h, (r & 31) * 32, (r >> 5) * 32, tid);
    } else if (b < PB4) {
        int r = b - PB3;
        int z = r >> 10, rr = r & 1023;
        do_transpose(ew1 + (size_t)z * HD * HD, g_wteh + (size_t)z * HD * HD,
                     (rr & 31) * 32, (rr >> 5) * 32, tid);
    } else if (b < PB5) {
        int g = (b - PB4) * 256 + tid;
        int gw = g >> 5, lane = g & 31;
        if (gw < EE * HD) {
            const float* row = ew2 + (size_t)gw * HD;
#pragma unroll
            for (int t = 0; t < TT; t++) {
                float a = 0.f;
                for (int o = lane; o < HD; o += 32) a += row[o] * tw[t * HD + o];
#pragma unroll
                for (int off = 16; off; off >>= 1) a += __shfl_down_sync(0xffffffffu, a, off);
                if (lane == 0) g_w2t[(size_t)gw * TT + t] = a;
            }
        }
    } else {
        if (tid < EE * TT) {
            int e = tid / TT, t = tid - TT * e;
            float a = 0.f;
            for (int o = 0; o < HD; o++) a += eb2[e * HD + o] * tw[t * HD + o];
            g_b2dot[tid] = a;
        }
    }
}

// ======================= gates / final / finalize =======================
__global__ __launch_bounds__(256) void gates_kernel(const float* __restrict__ wg) {
    int warp = threadIdx.x >> 5, lane = threadIdx.x & 31;
    int n = blockIdx.x * 8 + warp;
    const float* xr = g_x + (size_t)n * HD;
    float xv[32];
#pragma unroll
    for (int i = 0; i < 32; i++) xv[i] = xr[i * 32 + lane];
    float lg[18];
    for (int te = 0; te < 18; te++) {
        int t = te / 6, e = te - 6 * t;
        float acc = 0.f;
#pragma unroll
        for (int i = 0; i < 32; i++)
            acc += xv[i] * wg[((size_t)t * HD + i * 32 + lane) * EE + e];
#pragma unroll
        for (int off = 16; off; off >>= 1) acc += __shfl_down_sync(0xffffffffu, acc, off);
        lg[te] = acc;
    }
    if (lane == 0) {
        for (int t = 0; t < TT; t++) {
            float v[6];
#pragma unroll
            for (int e = 0; e < 6; e++) v[e] = lg[t * 6 + e];
            bool sel[6] = {false, false, false, false, false, false};
            float m = -1e30f;
            for (int r = 0; r < 3; r++) {  // strict >: first index wins (jax top_k)
                int bi = 0; float bv = -1e30f;
                for (int e = 0; e < 6; e++)
                    if (!sel[e] && v[e] > bv) { bv = v[e]; bi = e; }
                sel[bi] = true;
                if (r == 0) m = bv;
            }
            float sum = 0.f, gv[6];
            for (int e = 0; e < 6; e++) { gv[e] = sel[e] ? expf(v[e] - m) : 0.f; sum += gv[e]; }
            float inv = 1.f / sum;
            for (int e = 0; e < 6; e++) {
                float gg = gv[e] * inv;
                g_gates[(size_t)n * 18 + t * 6 + e] = gg;
                if (sel[e]) {
                    atomicAdd(&g_imp[t * 6 + e], gg);
                    atomicAdd(&g_load[t * 6 + e], 1.f);
                }
            }
        }
    }
}

__global__ void final_kernel(const float* __restrict__ scores,
                             const float* __restrict__ tower_b, float* __restrict__ out) {
    int b = blockIdx.x, c = threadIdx.x;
    int n = b * 64 + c;
    float sc[3];
#pragma unroll
    for (int t = 0; t < 3; t++) sc[t] = scores[(size_t)n * 3 + t];
    __shared__ float red[64];
    float mx[3];
    for (int t = 0; t < 3; t++) {
        red[c] = sc[t];
        __syncthreads();
        for (int off = 32; off; off >>= 1) {
            if (c < off) red[c] = fmaxf(red[c], red[c + off]);
            __syncthreads();
        }
        mx[t] = red[0];
        __syncthreads();
    }
    float zsum = 0.f, bsum = 0.f;
#pragma unroll
    for (int t = 0; t < 3; t++) {
        float z = tower_b[t];
#pragma unroll
        for (int e = 0; e < 6; e++)
            z += g_gates[(size_t)n * 18 + t * 6 + e] *
                 (g_s[(size_t)n * 18 + e * 3 + t] + g_b2dot[e * 3 + t]);
        float label = (sc[t] == mx[t]) ? 1.f : 0.f;
        bsum += fmaxf(z, 0.f) - z * label + log1pf(expf(-fabsf(z)));
        zsum += z;
    }
    out[1 + n] = 1.f / (1.f + expf(-zsum / 3.f));
    red[c] = bsum;
    __syncthreads();
    for (int off = 32; off; off >>= 1) {
        if (c < off) red[c] += red[c + off];
        __syncthreads();
    }
    if (c == 0) atomicAdd(&g_bce[0], red[0]);
}

__global__ void finalize_kernel(float* __restrict__ out) {
    if (threadIdx.x == 0 && blockIdx.x == 0) {
        float aux = 0.f;
        for (int t = 0; t < 3; t++) {
            for (int which = 0; which < 2; which++) {
                const float* v = which ? &g_load[t * 6] : &g_imp[t * 6];
                float m = 0.f;
                for (int e = 0; e < 6; e++) m += v[e];
                m *= (1.f / 6.f);
                float var = 0.f;
                for (int e = 0; e < 6; e++) { float d = v[e] - m; var += d * d; }
                var *= (1.f / 5.f);  // ddof=1
                aux += var / (m * m + 1e-10f);
            }
        }
        out[0] = g_bce[0] / 24576.f + 0.01f * aux;
    }
}

// ======================= launch =======================
extern "C" void kernel_launch(void* const* d_in, const int* in_sizes, int n_in,
                              void* d_out, int out_size) {
    const float* encs   = (const float*)d_in[0];
    const float* scores = (const float*)d_in[1];
    const float* fc1_w  = (const float*)d_in[2];
    const float* fc1_b  = (const float*)d_in[3];
    const float* fc2_w  = (const float*)d_in[4];
    const float* fc2_b  = (const float*)d_in[5];
    const float* w_gate = (const float*)d_in[6];
    const float* ew1    = (const float*)d_in[7];
    const float* eb1    = (const float*)d_in[8];
    const float* ew2    = (const float*)d_in[9];
    const float* eb2    = (const float*)d_in[10];
    const float* tw     = (const float*)d_in[11];
    const float* tb     = (const float*)d_in[12];
    float* out = (float*)d_out;

    cudaFuncSetAttribute(gemm_mma<0>, cudaFuncAttributeMaxDynamicSharedMemorySize, GSMEM);
    cudaFuncSetAttribute(gemm_mma<1>, cudaFuncAttributeMaxDynamicSharedMemorySize, GSMEM);
    cudaFuncSetAttribute(gemm_mma<2>, cudaFuncAttributeMaxDynamicSharedMemorySize, GSMEM);

    dim3 gfc(HD / BN, NT / BM, 1);
    dim3 ge(HD / BN, NT / BM, EE);

    prep_kernel<<<PB6, 256>>>(encs, fc1_w, fc2_w, ew1, ew2, eb2, tw);
    gemm_mma<1><<<gfc, 256, GSMEM>>>(fc1_b);                               // x1
    gemm_mma<0><<<gfc, 256, GSMEM>>>(fc2_b);                               // x
    gates_kernel<<<NT / 8, 256>>>(w_gate);
    gemm_mma<2><<<ge, 256, GSMEM>>>(eb1);                                  // experts
    final_kernel<<<128, 64>>>(scores, tb, out);
    finalize_kernel<<<1, 32>>>(out);
}

// round 16
// speedup vs baseline: 1.1696x; 1.0285x over previous
#include <cuda_runtime.h>
#include <cuda_fp16.h>
#include <math.h>
#include <cstdint>

#define NT 8192   // B*C tokens
#define HD 1024
#define TT 3
#define EE 6

constexpr int KB = HD / 64;  // k-blocks per operand row (tiles of 64 halves = 128 B)

// ---- scratch (device globals; no allocation allowed) ----
// Tiled-swizzled fp16 operands: tile = 128 rows x 128 B (8192 halves),
// tile index = row_blk * KB + k_blk; within tile: off = r*128 + (2c ^ ((r&7)<<4)).
__device__ __align__(128) __half g_ench[NT * HD];
__device__ __align__(128) __half g_x1h[NT * HD];
__device__ float  g_x[NT * HD];          // fp32 shared-bottom out, LINEAR (for gates)
__device__ __align__(128) __half g_xh[NT * HD];
__device__ __align__(128) __half g_wt1h[HD * HD];
__device__ __align__(128) __half g_wt2h[HD * HD];
__device__ __align__(128) __half g_wteh[EE * HD * HD];
__device__ float g_gates[NT * TT * EE];
__device__ float g_s[NT * EE * TT];
__device__ float g_w2t[EE * HD * TT];
__device__ float g_b2dot[EE * TT];
__device__ float g_imp[TT * EE];
__device__ float g_load[TT * EE];
__device__ float g_bce[1];

// ======================= helpers =======================
__device__ __forceinline__ uint32_t smem_u32(const void* p) {
    uint32_t a;
    asm("{ .reg .u64 t; cvta.to.shared.u64 t, %1; cvt.u32.u64 %0, t; }" : "=r"(a) : "l"(p));
    return a;
}
#define MBAR_INIT(a, c) asm volatile("mbarrier.init.shared.b64 [%0], %1;" :: "r"((uint32_t)(a)), "r"((uint32_t)(c)) : "memory")
#define MBAR_INVAL(a) asm volatile("mbarrier.inval.shared.b64 [%0];" :: "r"((uint32_t)(a)) : "memory")
#define MBAR_EXPECT_TX(a, n) asm volatile("mbarrier.arrive.expect_tx.shared.b64 _, [%0], %1;" :: "r"((uint32_t)(a)), "r"((uint32_t)(n)) : "memory")
#define MBAR_ARRIVE(a) asm volatile("mbarrier.arrive.shared.b64 _, [%0];" :: "r"((uint32_t)(a)) : "memory")
#define MBAR_WAIT(a, ph) do {                                              \
    uint32_t _m = (uint32_t)(a), _p = (uint32_t)(ph), _d;                  \
    asm volatile("{ .reg .pred p; mbarrier.try_wait.parity.acquire.cta.shared::cta.b64 p, [%1], %2; selp.b32 %0,1,0,p; }" \
                 : "=r"(_d) : "r"(_m), "r"(_p) : "memory");                \
    if (!_d) {                                                             \
        asm volatile("{ .reg .pred P1; WL%=: mbarrier.try_wait.parity.acquire.cta.shared::cta.b64 P1, [%0], %1, 0x989680; @P1 bra.uni WD%=; bra.uni WL%=; WD%=: }" \
                     :: "r"(_m), "r"(_p) : "memory");                      \
    }                                                                      \
} while (0)
__device__ __forceinline__ void bulk_ld(uint32_t dst, const void* src, uint32_t bytes,
                                        uint32_t mbar) {
    asm volatile(
        "cp.async.bulk.shared::cluster.global.mbarrier::complete_tx::bytes [%0], [%1], %2, [%3];"
        :: "r"(dst), "l"(src), "r"(bytes), "r"(mbar) : "memory");
}

__device__ __forceinline__ void mma16(float* c, const uint32_t* a, const uint32_t* b) {
    asm volatile(
        "mma.sync.aligned.m16n8k16.row.col.f32.f16.f16.f32 "
        "{%0,%1,%2,%3}, {%4,%5,%6,%7}, {%8,%9}, {%0,%1,%2,%3};"
        : "+f"(c[0]), "+f"(c[1]), "+f"(c[2]), "+f"(c[3])
        : "r"(a[0]), "r"(a[1]), "r"(a[2]), "r"(a[3]), "r"(b[0]), "r"(b[1]));
}
__device__ __forceinline__ void ldsm4(uint32_t* r, uint32_t addr) {
    asm volatile("ldmatrix.sync.aligned.m8n8.x4.shared.b16 {%0,%1,%2,%3}, [%4];"
                 : "=r"(r[0]), "=r"(r[1]), "=r"(r[2]), "=r"(r[3]) : "r"(addr));
}

// half-index offset of element (r, c-half) inside tiled-swizzled operand
__device__ __forceinline__ size_t tile_off(int row_blk, int k_blk, int r, int c) {
    uint32_t b = (uint32_t)(2 * c) ^ (uint32_t)((r & 7) << 4);
    return ((size_t)(row_blk * KB + k_blk) << 13) + ((uint32_t)r << 6) + (b >> 1);
}

// ======================= fp16 mma.sync GEMM (round-13 config) =======================
constexpr int BM = 128, BN = 128;
constexpr int BKH = 64;                  // k-halves per slab = one tile column
constexpr int NS = HD / BKH;             // 16 slabs
constexpr int TILE_BYTES = 16384;
constexpr int STG_B = 2 * TILE_BYTES;    // A tile + B tile
constexpr int CTRL = 1024;               // mbars: data at +0,8,16; free at +32,40,48
constexpr int GSMEM = CTRL + 3 * STG_B;  // 99328 B (2 CTAs/SM)

// MODE 0: fc2 (A=g_x1h -> g_x fp32 + g_xh tiled)  MODE 1: fc1 (A=g_ench -> g_x1h tiled, relu)
// MODE 2: expert (A=g_xh, bias+relu, fused s-epilogue)
template <int MODE>
__global__ __launch_bounds__(256, 2) void gemm_mma(const float* __restrict__ bias_in) {
    extern __shared__ __align__(16) char smb[];
    const uint32_t sb = smem_u32(smb);
    float* smf = (float*)smb;
    const int tid = threadIdx.x;
    const int wid = tid >> 5, lane = tid & 31;
    const int wm = wid >> 2, wn = wid & 3;     // warp grid 2(M) x 4(N)
    const int gr = lane >> 2, tq = lane & 3;   // quad row / quad col
    const int e = blockIdx.z;
    const int rb = blockIdx.y * BM, cb = blockIdx.x * BN;

    const __half* A = (MODE == 1) ? g_ench : (MODE == 0 ? g_x1h : g_xh);
    const __half* Bw = (MODE == 1) ? g_wt1h
                                   : (MODE == 0 ? g_wt2h : g_wteh + (size_t)e * HD * HD);
    const float* bp = bias_in + (MODE == 2 ? (size_t)e * HD : 0);

    float C[4][4][4];
#pragma unroll
    for (int i = 0; i < 4; i++)
#pragma unroll
        for (int j = 0; j < 4; j++)
#pragma unroll
            for (int q = 0; q < 4; q++) C[i][j][q] = 0.f;

    // ldmatrix lane addressing (pre-swizzled tiles; swz constant per lane)
    const uint32_t swz = (uint32_t)((lane & 7) << 4);
    const uint32_t a_row_off = (uint32_t)((wm * 64 + (lane & 15)) * 128);
    const uint32_t a_seg = (uint32_t)((lane >> 4) << 4);
    const uint32_t b_row_off =
        (uint32_t)((wn * 32 + ((lane >> 4) << 3) + (lane & 7)) * 128);
    const uint32_t b_seg = (uint32_t)(((lane >> 3) & 1) << 4);

    if (tid == 0) {
        MBAR_INIT(sb + 0, 1);    // data[0]
        MBAR_INIT(sb + 8, 1);    // data[1]
        MBAR_INIT(sb + 16, 1);   // data[2]
        MBAR_INIT(sb + 32, 8);   // free[0]
        MBAR_INIT(sb + 40, 8);   // free[1]
        MBAR_INIT(sb + 48, 8);   // free[2]
    }
    __syncthreads();

    auto issue = [&](int p, int s) {  // load slab p into stage s (single thread)
        uint32_t mb = sb + 8 * s;
        uint32_t stg = sb + CTRL + s * STG_B;
        MBAR_EXPECT_TX(mb, (uint32_t)STG_B);
        bulk_ld(stg, A + (((size_t)(blockIdx.y * KB + p)) << 13), TILE_BYTES, mb);
        bulk_ld(stg + TILE_BYTES, Bw + (((size_t)(blockIdx.x * KB + p)) << 13), TILE_BYTES, mb);
    };

    if (tid == 0) { issue(0, 0); issue(1, 1); }

    for (int i = 0; i < NS; i++) {
        const int s = i % 3;
        // producer: issue slab i+2 into its stage as soon as that stage is free
        if (tid == 0 && i + 2 < NS) {
            const int j = i + 2;
            if (j >= 3) MBAR_WAIT(sb + 32 + 8 * (j % 3), ((j / 3) - 1) & 1);
            issue(j, j % 3);
        }
        MBAR_WAIT(sb + 8 * s, (i / 3) & 1);   // slab i data resident

        const uint32_t As_u = sb + CTRL + s * STG_B;
        const uint32_t Bs_u = As_u + TILE_BYTES;
#pragma unroll
        for (int ks = 0; ks < 4; ks++) {
            const uint32_t a_col = ((uint32_t)(ks * 32) + a_seg) ^ swz;
            const uint32_t b_col = ((uint32_t)(ks * 32) + b_seg) ^ swz;
            uint32_t a[4][4], b[2][4];
#pragma unroll
            for (int mt = 0; mt < 4; mt++)
                ldsm4(a[mt], As_u + a_row_off + (uint32_t)(mt * 2048) + a_col);
#pragma unroll
            for (int np = 0; np < 2; np++)
                ldsm4(b[np], Bs_u + b_row_off + (uint32_t)(np * 2048) + b_col);
#pragma unroll
            for (int mt = 0; mt < 4; mt++) {
#pragma unroll
                for (int np = 0; np < 2; np++) {
                    mma16(C[mt][2 * np + 0], a[mt], &b[np][0]);
                    mma16(C[mt][2 * np + 1], a[mt], &b[np][2]);
                }
            }
        }
        if (lane == 0) MBAR_ARRIVE(sb + 32 + 8 * s);  // this warp done with stage s
    }
    __syncthreads();  // all warps past the loop; no pending stage reuse
    if (tid == 0) {
        MBAR_INVAL(sb + 0);  MBAR_INVAL(sb + 8);  MBAR_INVAL(sb + 16);
        MBAR_INVAL(sb + 32); MBAR_INVAL(sb + 40); MBAR_INVAL(sb + 48);
    }
    __syncthreads();

    // ---- epilogue ----
    if (MODE == 2) {
        float* w2t_s = smf;            // 384
        float* bias_s = smf + 384;     // 128
        float* sred = smf + 512;       // 128*12
        if (tid < 128) bias_s[tid] = bp[cb + tid];
        for (int idx = tid; idx < 384; idx += 256)
            w2t_s[idx] = g_w2t[(size_t)e * HD * 3 + (size_t)cb * 3 + idx];
        __syncthreads();
#pragma unroll
        for (int mt = 0; mt < 4; mt++) {
#pragma unroll
            for (int pair = 0; pair < 2; pair++) {
                float p0 = 0.f, p1 = 0.f, p2 = 0.f;
#pragma unroll
                for (int nt = 0; nt < 4; nt++) {
                    int cl = wn * 32 + nt * 8 + tq * 2;
                    float h0 = fmaxf(C[mt][nt][pair * 2 + 0] + bias_s[cl], 0.f);
                    float h1 = fmaxf(C[mt][nt][pair * 2 + 1] + bias_s[cl + 1], 0.f);
                    p0 += h0 * w2t_s[cl * 3 + 0] + h1 * w2t_s[(cl + 1) * 3 + 0];
                    p1 += h0 * w2t_s[cl * 3 + 1] + h1 * w2t_s[(cl + 1) * 3 + 1];
                    p2 += h0 * w2t_s[cl * 3 + 2] + h1 * w2t_s[(cl + 1) * 3 + 2];
                }
                p0 += __shfl_down_sync(0xffffffffu, p0, 2);
                p0 += __shfl_down_sync(0xffffffffu, p0, 1);
                p1 += __shfl_down_sync(0xffffffffu, p1, 2);
                p1 += __shfl_down_sync(0xffffffffu, p1, 1);
                p2 += __shfl_down_sync(0xffffffffu, p2, 2);
                p2 += __shfl_down_sync(0xffffffffu, p2, 1);
                if (tq == 0) {
                    int rl = wm * 64 + mt * 16 + pair * 8 + gr;
                    sred[rl * 12 + wn * 3 + 0] = p0;
                    sred[rl * 12 + wn * 3 + 1] = p1;
                    sred[rl * 12 + wn * 3 + 2] = p2;
                }
            }
        }
        __syncthreads();
        if (tid < 128) {
#pragma unroll
            for (int t = 0; t < 3; t++) {
                float s = sred[tid * 12 + t] + sred[tid * 12 + 3 + t] +
                          sred[tid * 12 + 6 + t] + sred[tid * 12 + 9 + t];
                atomicAdd(&g_s[(size_t)(rb + tid) * 18 + e * 3 + t], s);
            }
        }
    } else {
        float* bias_s = smf;
        if (tid < 128) bias_s[tid] = bp[cb + tid];
        __syncthreads();
#pragma unroll
        for (int mt = 0; mt < 4; mt++) {
#pragma unroll
            for (int nt = 0; nt < 4; nt++) {
                int r0 = wm * 64 + mt * 16 + gr;         // within-CTA rows (<128)
                int cl = wn * 32 + nt * 8 + tq * 2;
                int kcol = cb + cl;
                int k_blk = kcol >> 6, c = kcol & 63;
                float v0 = C[mt][nt][0] + bias_s[cl];
                float v1 = C[mt][nt][1] + bias_s[cl + 1];
                float v2 = C[mt][nt][2] + bias_s[cl];
                float v3 = C[mt][nt][3] + bias_s[cl + 1];
                if (MODE == 1) {
                    v0 = fmaxf(v0, 0.f); v1 = fmaxf(v1, 0.f);
                    v2 = fmaxf(v2, 0.f); v3 = fmaxf(v3, 0.f);
                }
                __half2 h0 = __halves2half2(__float2half_rn(v0), __float2half_rn(v1));
                __half2 h1 = __halves2half2(__float2half_rn(v2), __float2half_rn(v3));
                __half* outh = (MODE == 1) ? g_x1h : g_xh;
                *(__half2*)(outh + tile_off(blockIdx.y, k_blk, r0, c)) = h0;
                *(__half2*)(outh + tile_off(blockIdx.y, k_blk, r0 + 8, c)) = h1;
                if (MODE == 0) {
                    int row = rb + r0;
                    *(float2*)(g_x + (size_t)row * HD + kcol) = make_float2(v0, v1);
                    *(float2*)(g_x + (size_t)(row + 8) * HD + kcol) = make_float2(v2, v3);
                }
            }
        }
    }
}

// ======================= fused prep kernel =======================
constexpr int PB0 = 576, PB1 = PB0 + 4096, PB2 = PB1 + 1024, PB3 = PB2 + 1024,
              PB4 = PB3 + 6144, PB5 = PB4 + 768, PB6 = PB5 + 1;

__device__ void do_transpose(const float* __restrict__ Ws, __half* __restrict__ Ts,
                             int bx, int by, int tid) {
    __shared__ float t[32][33];
    int tx = tid & 31, ty = tid >> 5;  // (32, 8)
#pragma unroll
    for (int j = 0; j < 4; j++)
        t[ty + 8 * j][tx] = Ws[(size_t)(by + ty + 8 * j) * HD + bx + tx];
    __syncthreads();
#pragma unroll
    for (int j = 0; j < 4; j++) {
        int nrow = bx + ty + 8 * j;
        int kcol = by + tx;
        Ts[tile_off(nrow >> 7, kcol >> 6, nrow & 127, kcol & 63)] =
            __float2half_rn(t[tx][ty + 8 * j]);
    }
}

__global__ __launch_bounds__(256) void prep_kernel(
    const float* __restrict__ encs, const float* __restrict__ fc1_w,
    const float* __restrict__ fc2_w, const float* __restrict__ ew1,
    const float* __restrict__ ew2, const float* __restrict__ eb2,
    const float* __restrict__ tw) {
    const int b = blockIdx.x, tid = threadIdx.x;
    if (b < PB0) {
        int idx = b * 256 + tid;
        if (idx < NT * EE * TT) g_s[idx] = 0.f;
        if (idx < TT * EE) { g_imp[idx] = 0.f; g_load[idx] = 0.f; }
        if (idx == 0) g_bce[0] = 0.f;
    } else if (b < PB1) {
        int gid = (b - PB0) * 256 + tid;
        int n = gid >> 7, s8 = gid & 127, k = s8 * 8;
        float4 v0 = *(const float4*)(encs + (size_t)n * HD + k);
        float4 v1 = *(const float4*)(encs + (size_t)n * HD + k + 4);
        __half2 h[4];
        h[0] = __halves2half2(__float2half_rn(v0.x), __float2half_rn(v0.y));
        h[1] = __halves2half2(__float2half_rn(v0.z), __float2half_rn(v0.w));
        h[2] = __halves2half2(__float2half_rn(v1.x), __float2half_rn(v1.y));
        h[3] = __halves2half2(__float2half_rn(v1.z), __float2half_rn(v1.w));
        *(uint4*)(g_ench + tile_off(n >> 7, k >> 6, n & 127, k & 63)) = *(uint4*)h;
    } else if (b < PB2) {
        int r = b - PB1;
        do_transpose(fc1_w, g_wt1h, (r & 31) * 32, (r >> 5) * 32, tid);
    } else if (b < PB3) {
        int r = b - PB2;
        do_transpose(fc2_w, g_wt2h, (r & 31) * 32, (r >> 5) * 32, tid);
    } else if (b < PB4) {
        int r = b - PB3;
        int z = r >> 10, rr = r & 1023;
        do_transpose(ew1 + (size_t)z * HD * HD, g_wteh + (size_t)z * HD * HD,
                     (rr & 31) * 32, (rr >> 5) * 32, tid);
    } else if (b < PB5) {
        int g = (b - PB4) * 256 + tid;
        int gw = g >> 5, lane = g & 31;
        if (gw < EE * HD) {
            const float* row = ew2 + (size_t)gw * HD;
#pragma unroll
            for (int t = 0; t < TT; t++) {
                float a = 0.f;
                for (int o = lane; o < HD; o += 32) a += row[o] * tw[t * HD + o];
#pragma unroll
                for (int off = 16; off; off >>= 1) a += __shfl_down_sync(0xffffffffu, a, off);
                if (lane == 0) g_w2t[(size_t)gw * TT + t] = a;
            }
        }
    } else {
        if (tid < EE * TT) {
            int e = tid / TT, t = tid - TT * e;
            float a = 0.f;
            for (int o = 0; o < HD; o++) a += eb2[e * HD + o] * tw[t * HD + o];
            g_b2dot[tid] = a;
        }
    }
}

// ======================= gates (smem-cached w_gate) =======================
// Block caches permuted w_gate in smem: wgs[k*18 + t*6+e]. 128 blocks x 8 warps,
// 8 tokens per warp. Same per-lane strided accumulation + shuffle tree as before
// (identical arithmetic). imp/load aggregated in smem, 36 global atomics/block.
constexpr int GATES_SMEM = (HD * 18 + 2 * 18) * 4;  // 73872 B

__global__ __launch_bounds__(256) void gates_kernel(const float* __restrict__ wg) {
    extern __shared__ float wgs[];          // HD*18
    float* simp = wgs + HD * 18;            // 18
    float* sload = simp + 18;               // 18
    const int tid = threadIdx.x;
    if (tid < 18) { simp[tid] = 0.f; sload[tid] = 0.f; }
    // permuted coalesced load: src idx = t*HD*6 + k*6 + e -> dst k*18 + t*6 + e
    for (int idx = tid; idx < TT * HD * EE; idx += 256) {
        int t = idx / (HD * EE);
        int rem = idx - t * HD * EE;
        int k = rem / EE, e = rem - EE * k;
        wgs[k * 18 + t * 6 + e] = wg[idx];
    }
    __syncthreads();

    const int warp = tid >> 5, lane = tid & 31;
    for (int tok = 0; tok < 8; tok++) {
        const int n = (blockIdx.x * 8 + warp) * 8 + tok;
        const float* xr = g_x + (size_t)n * HD;
        float acc[18];
#pragma unroll
        for (int j = 0; j < 18; j++) acc[j] = 0.f;
        for (int i = 0; i < 32; i++) {
            float xv = xr[i * 32 + lane];
            const float* w = wgs + (i * 32 + lane) * 18;
#pragma unroll
            for (int j = 0; j < 18; j++) acc[j] += xv * w[j];
        }
#pragma unroll
        for (int j = 0; j < 18; j++) {
#pragma unroll
            for (int off = 16; off; off >>= 1)
                acc[j] += __shfl_down_sync(0xffffffffu, acc[j], off);
        }
        if (lane == 0) {
            for (int t = 0; t < TT; t++) {
                float v[6];
#pragma unroll
                for (int e = 0; e < 6; e++) v[e] = acc[t * 6 + e];
                bool sel[6] = {false, false, false, false, false, false};
                float m = -1e30f;
                for (int r = 0; r < 3; r++) {  // strict >: first index wins (jax top_k)
                    int bi = 0; float bv = -1e30f;
                    for (int e = 0; e < 6; e++)
                        if (!sel[e] && v[e] > bv) { bv = v[e]; bi = e; }
                    sel[bi] = true;
                    if (r == 0) m = bv;
                }
                float sum = 0.f, gv[6];
                for (int e = 0; e < 6; e++) {
                    gv[e] = sel[e] ? expf(v[e] - m) : 0.f;
                    sum += gv[e];
                }
                float inv = 1.f / sum;
                for (int e = 0; e < 6; e++) {
                    float gg = gv[e] * inv;
                    g_gates[(size_t)n * 18 + t * 6 + e] = gg;
                    if (sel[e]) {
                        atomicAdd(&simp[t * 6 + e], gg);
                        atomicAdd(&sload[t * 6 + e], 1.f);
                    }
                }
            }
        }
    }
    __syncthreads();
    if (tid < 18) {
        atomicAdd(&g_imp[tid], simp[tid]);
        atomicAdd(&g_load[tid], sload[tid]);
    }
}

// ======================= final / finalize =======================
__global__ void final_kernel(const float* __restrict__ scores,
                             const float* __restrict__ tower_b, float* __restrict__ out) {
    int b = blockIdx.x, c = threadIdx.x;
    int n = b * 64 + c;
    float sc[3];
#pragma unroll
    for (int t = 0; t < 3; t++) sc[t] = scores[(size_t)n * 3 + t];
    __shared__ float red[64];
    float mx[3];
    for (int t = 0; t < 3; t++) {
        red[c] = sc[t];
        __syncthreads();
        for (int off = 32; off; off >>= 1) {
            if (c < off) red[c] = fmaxf(red[c], red[c + off]);
            __syncthreads();
        }
        mx[t] = red[0];
        __syncthreads();
    }
    float zsum = 0.f, bsum = 0.f;
#pragma unroll
    for (int t = 0; t < 3; t++) {
        float z = tower_b[t];
#pragma unroll
        for (int e = 0; e < 6; e++)
            z += g_gates[(size_t)n * 18 + t * 6 + e] *
                 (g_s[(size_t)n * 18 + e * 3 + t] + g_b2dot[e * 3 + t]);
        float label = (sc[t] == mx[t]) ? 1.f : 0.f;
        bsum += fmaxf(z, 0.f) - z * label + log1pf(expf(-fabsf(z)));
        zsum += z;
    }
    out[1 + n] = 1.f / (1.f + expf(-zsum / 3.f));
    red[c] = bsum;
    __syncthreads();
    for (int off = 32; off; off >>= 1) {
        if (c < off) red[c] += red[c + off];
        __syncthreads();
    }
    if (c == 0) atomicAdd(&g_bce[0], red[0]);
}

__global__ void finalize_kernel(float* __restrict__ out) {
    if (threadIdx.x == 0 && blockIdx.x == 0) {
        float aux = 0.f;
        for (int t = 0; t < 3; t++) {
            for (int which = 0; which < 2; which++) {
                const float* v = which ? &g_load[t * 6] : &g_imp[t * 6];
                float m = 0.f;
                for (int e = 0; e < 6; e++) m += v[e];
                m *= (1.f / 6.f);
                float var = 0.f;
                for (int e = 0; e < 6; e++) { float d = v[e] - m; var += d * d; }
                var *= (1.f / 5.f);  // ddof=1
                aux += var / (m * m + 1e-10f);
            }
        }
        out[0] = g_bce[0] / 24576.f + 0.01f * aux;
    }
}

// ======================= launch =======================
extern "C" void kernel_launch(void* const* d_in, const int* in_sizes, int n_in,
                              void* d_out, int out_size) {
    const float* encs   = (const float*)d_in[0];
    const float* scores = (const float*)d_in[1];
    const float* fc1_w  = (const float*)d_in[2];
    const float* fc1_b  = (const float*)d_in[3];
    const float* fc2_w  = (const float*)d_in[4];
    const float* fc2_b  = (const float*)d_in[5];
    const float* w_gate = (const float*)d_in[6];
    const float* ew1    = (const float*)d_in[7];
    const float* eb1    = (const float*)d_in[8];
    const float* ew2    = (const float*)d_in[9];
    const float* eb2    = (const float*)d_in[10];
    const float* tw     = (const float*)d_in[11];
    const float* tb     = (const float*)d_in[12];
    float* out = (float*)d_out;

    cudaFuncSetAttribute(gemm_mma<0>, cudaFuncAttributeMaxDynamicSharedMemorySize, GSMEM);
    cudaFuncSetAttribute(gemm_mma<1>, cudaFuncAttributeMaxDynamicSharedMemorySize, GSMEM);
    cudaFuncSetAttribute(gemm_mma<2>, cudaFuncAttributeMaxDynamicSharedMemorySize, GSMEM);
    cudaFuncSetAttribute(gates_kernel, cudaFuncAttributeMaxDynamicSharedMemorySize, GATES_SMEM);

    dim3 gfc(HD / BN, NT / BM, 1);
    dim3 ge(HD / BN, NT / BM, EE);

    prep_kernel<<<PB6, 256>>>(encs, fc1_w, fc2_w, ew1, ew2, eb2, tw);
    gemm_mma<1><<<gfc, 256, GSMEM>>>(fc1_b);                               // x1
    gemm_mma<0><<<gfc, 256, GSMEM>>>(fc2_b);                               // x
    gates_kernel<<<128, 256, GATES_SMEM>>>(w_gate);
    gemm_mma<2><<<ge, 256, GSMEM>>>(eb1);                                  // experts
    final_kernel<<<128, 64>>>(scores, tb, out);
    finalize_kernel<<<1, 32>>>(out);
}